// round 4
// baseline (speedup 1.0000x reference)
#include <cuda_runtime.h>

// out[b,f] = x[b,f] * (log_sigma[f] < 1.0f ? e : 1.0f)
// BATCH=65536, N_FEATURES=4096. Pure HBM stream (1 GiB in + 1 GiB out).
//
// R4: 256-bit global loads/stores (ld/st.global.v8.f32, sm_100+) to halve
// L1tex wavefront count and present 1KB/warp bursts to L2/HBM.
// Grid-stride, 8192 blocks; per-thread column (in v8 units) is loop-invariant
// since total threads (2^21) is a multiple of V8_PER_ROW (512).

#define N_FEATURES  4096
#define V8_PER_ROW  (N_FEATURES / 8)             // 512, power of two
#define TOTAL_V8    (65536LL * V8_PER_ROW)       // 2^25

#define THREADS  256
#define BLOCKS   8192                             // 2^21 threads
#define NTHREADS ((long long)THREADS * BLOCKS)    // 2^21, multiple of 512
#define ITERS    (TOTAL_V8 / NTHREADS)            // 16, exact

struct v8 { float f[8]; };

__device__ __forceinline__ v8 ldg_v8(const float* p) {
    v8 r;
    asm volatile("ld.global.nc.v8.f32 {%0,%1,%2,%3,%4,%5,%6,%7}, [%8];"
                 : "=f"(r.f[0]), "=f"(r.f[1]), "=f"(r.f[2]), "=f"(r.f[3]),
                   "=f"(r.f[4]), "=f"(r.f[5]), "=f"(r.f[6]), "=f"(r.f[7])
                 : "l"(p));
    return r;
}

__device__ __forceinline__ void stg_v8(float* p, const v8& v) {
    asm volatile("st.global.v8.f32 [%0], {%1,%2,%3,%4,%5,%6,%7,%8};"
                 :: "l"(p),
                    "f"(v.f[0]), "f"(v.f[1]), "f"(v.f[2]), "f"(v.f[3]),
                    "f"(v.f[4]), "f"(v.f[5]), "f"(v.f[6]), "f"(v.f[7])
                 : "memory");
}

__global__ void __launch_bounds__(THREADS)
svdropout2d_kernel(const float* __restrict__ x,
                   const float* __restrict__ log_sigma,
                   float* __restrict__ out)
{
    const float E = 2.71828182845904523536f;

    const long long i0 = (long long)blockIdx.x * THREADS + threadIdx.x;  // v8 index

    // Column (v8 units) invariant across the loop (stride % 512 == 0)
    const int c = (int)(i0 & (V8_PER_ROW - 1));

    v8 s;
    #pragma unroll
    for (int j = 0; j < 8; ++j) {
        float ls = __ldg(&log_sigma[c * 8 + j]);
        s.f[j] = (ls < 1.0f) ? E : 1.0f;
    }

    // 16 iterations, grouped x2 -> 2 independent 32B loads in flight per lane
    #pragma unroll 1
    for (int g = 0; g < (int)(ITERS / 2); ++g) {
        long long base = i0 + (long long)g * (2 * NTHREADS);

        v8 v0 = ldg_v8(x + (base + 0 * NTHREADS) * 8);
        v8 v1 = ldg_v8(x + (base + 1 * NTHREADS) * 8);

        #pragma unroll
        for (int j = 0; j < 8; ++j) v0.f[j] *= s.f[j];
        #pragma unroll
        for (int j = 0; j < 8; ++j) v1.f[j] *= s.f[j];

        stg_v8(out + (base + 0 * NTHREADS) * 8, v0);
        stg_v8(out + (base + 1 * NTHREADS) * 8, v1);
    }
}

extern "C" void kernel_launch(void* const* d_in, const int* in_sizes, int n_in,
                              void* d_out, int out_size)
{
    const float* x  = (const float*)d_in[0];
    const float* ls = (const float*)d_in[1];
    float* out      = (float*)d_out;

    svdropout2d_kernel<<<BLOCKS, THREADS>>>(x, ls, out);
}

// round 5
// speedup vs baseline: 1.0055x; 1.0055x over previous
#include <cuda_runtime.h>

// out[b,f] = x[b,f] * (log_sigma[f] < 1.0f ? e : 1.0f)
// BATCH=65536, N_FEATURES=4096 -> 2^26 float4. Pure HBM stream (2.15 GB).
//
// R5: R3 geometry (8192 blocks x 256 threads, float4, loop-invariant scale)
// but batch 8 loads then 8 stores per iteration: longer same-direction
// bursts at the memory controller (less R/W turnaround) and MLP=8.

#define N_FEATURES   4096
#define VEC4_PER_ROW (N_FEATURES / 4)            // 1024, power of two
#define TOTAL_VEC4   (65536LL * VEC4_PER_ROW)    // 2^26

#define THREADS  256
#define BLOCKS   8192                             // 2^21 threads total
#define NTHREADS ((long long)THREADS * BLOCKS)    // 2^21, multiple of 1024
#define ITERS    (TOTAL_VEC4 / NTHREADS)          // 32, exact
#define GRP      8                                // loads batched per group

__global__ void __launch_bounds__(THREADS)
svdropout2d_kernel(const float4* __restrict__ x,
                   const float4* __restrict__ log_sigma,
                   float4* __restrict__ out)
{
    const float E = 2.71828182845904523536f;

    const long long i0 = (long long)blockIdx.x * THREADS + threadIdx.x;

    // Column (float4 units) invariant across the loop (stride % 1024 == 0)
    const int c = (int)(i0 & (VEC4_PER_ROW - 1));
    const float4 ls = __ldg(&log_sigma[c]);

    float4 s;
    s.x = (ls.x < 1.0f) ? E : 1.0f;
    s.y = (ls.y < 1.0f) ? E : 1.0f;
    s.z = (ls.z < 1.0f) ? E : 1.0f;
    s.w = (ls.w < 1.0f) ? E : 1.0f;

    // 32 iterations as 4 groups of 8: 8 loads in flight, then 8 stores.
    #pragma unroll 1
    for (int g = 0; g < (int)(ITERS / GRP); ++g) {
        long long base = i0 + (long long)g * (GRP * NTHREADS);

        float4 v[GRP];
        #pragma unroll
        for (int j = 0; j < GRP; ++j)
            v[j] = __ldcs(&x[base + (long long)j * NTHREADS]);

        #pragma unroll
        for (int j = 0; j < GRP; ++j) {
            v[j].x *= s.x; v[j].y *= s.y; v[j].z *= s.z; v[j].w *= s.w;
        }

        #pragma unroll
        for (int j = 0; j < GRP; ++j)
            __stcs(&out[base + (long long)j * NTHREADS], v[j]);
    }
}

extern "C" void kernel_launch(void* const* d_in, const int* in_sizes, int n_in,
                              void* d_out, int out_size)
{
    const float4* x  = (const float4*)d_in[0];
    const float4* ls = (const float4*)d_in[1];
    float4* out      = (float4*)d_out;

    svdropout2d_kernel<<<BLOCKS, THREADS>>>(x, ls, out);
}

// round 6
// speedup vs baseline: 1.0122x; 1.0067x over previous
#include <cuda_runtime.h>

// out[b,f] = x[b,f] * (log_sigma[f] < 1.0f ? e : 1.0f)
// BATCH=65536, N_FEATURES=4096 -> 2^26 float4. Pure HBM stream (2.15 GB).
//
// R6: R3 structure (float4, ldcs/stcs, loop-invariant per-thread scale,
// GRP=4 in-flight loads) with 16384 blocks: finer wave granularity
// (~halved tail quantum) and lower register pressure.

#define N_FEATURES   4096
#define VEC4_PER_ROW (N_FEATURES / 4)            // 1024, power of two
#define TOTAL_VEC4   (65536LL * VEC4_PER_ROW)    // 2^26

#define THREADS  256
#define BLOCKS   16384                            // 2^22 threads total
#define NTHREADS ((long long)THREADS * BLOCKS)    // 2^22, multiple of 1024
#define ITERS    (TOTAL_VEC4 / NTHREADS)          // 16, exact
#define GRP      4

__global__ void __launch_bounds__(THREADS)
svdropout2d_kernel(const float4* __restrict__ x,
                   const float4* __restrict__ log_sigma,
                   float4* __restrict__ out)
{
    const float E = 2.71828182845904523536f;

    const long long i0 = (long long)blockIdx.x * THREADS + threadIdx.x;

    // Column (float4 units) invariant across the loop (stride % 1024 == 0)
    const int c = (int)(i0 & (VEC4_PER_ROW - 1));
    const float4 ls = __ldg(&log_sigma[c]);

    float4 s;
    s.x = (ls.x < 1.0f) ? E : 1.0f;
    s.y = (ls.y < 1.0f) ? E : 1.0f;
    s.z = (ls.z < 1.0f) ? E : 1.0f;
    s.w = (ls.w < 1.0f) ? E : 1.0f;

    // 16 iterations as 4 groups of 4: 4 independent loads in flight.
    #pragma unroll 1
    for (int g = 0; g < (int)(ITERS / GRP); ++g) {
        long long base = i0 + (long long)g * (GRP * NTHREADS);

        float4 v0 = __ldcs(&x[base + 0 * NTHREADS]);
        float4 v1 = __ldcs(&x[base + 1 * NTHREADS]);
        float4 v2 = __ldcs(&x[base + 2 * NTHREADS]);
        float4 v3 = __ldcs(&x[base + 3 * NTHREADS]);

        v0.x *= s.x; v0.y *= s.y; v0.z *= s.z; v0.w *= s.w;
        v1.x *= s.x; v1.y *= s.y; v1.z *= s.z; v1.w *= s.w;
        v2.x *= s.x; v2.y *= s.y; v2.z *= s.z; v2.w *= s.w;
        v3.x *= s.x; v3.y *= s.y; v3.z *= s.z; v3.w *= s.w;

        __stcs(&out[base + 0 * NTHREADS], v0);
        __stcs(&out[base + 1 * NTHREADS], v1);
        __stcs(&out[base + 2 * NTHREADS], v2);
        __stcs(&out[base + 3 * NTHREADS], v3);
    }
}

extern "C" void kernel_launch(void* const* d_in, const int* in_sizes, int n_in,
                              void* d_out, int out_size)
{
    const float4* x  = (const float4*)d_in[0];
    const float4* ls = (const float4*)d_in[1];
    float4* out      = (float4*)d_out;

    svdropout2d_kernel<<<BLOCKS, THREADS>>>(x, ls, out);
}